// round 2
// baseline (speedup 1.0000x reference)
#include <cuda_runtime.h>
#include <math.h>

#define B_SZ   16384
#define F_CAT  26
#define F_CONT 13
#define VOCAB  100000
#define DIM    64
#define IN_DIM 2496      // (26+13)*64
#define H1N    1024
#define H2N    512
#define BN_EPS 1e-5f

// ---------------- scratch (device globals; no runtime allocation) ----------------
__device__ __align__(128) float g_E [(size_t)B_SZ * IN_DIM];   // 163 MB
__device__ __align__(128) float g_Z1[(size_t)B_SZ * H1N];      // 67 MB (in-place BN+ReLU)
__device__ __align__(128) float g_Z2[(size_t)B_SZ * H2N];      // 33 MB (in-place BN+ReLU)
__device__ __align__(128) float g_fm[B_SZ];
__device__ __align__(128) float g_psum[64 * H1N];              // partial sums (reused for layer2)
__device__ __align__(128) float g_pss [64 * H1N];
__device__ __align__(128) float g_sum [H1N];
__device__ __align__(128) float g_ss  [H1N];

// ---------------- kernel 1: embedding gather + FM terms + build E ----------------
// one block (64 threads) per sample; thread d owns embedding dim d
__global__ __launch_bounds__(64) void embed_fm_kernel(
    const int*   __restrict__ cat_feats,   // [B, 26]
    const float* __restrict__ cont_feats,  // [B, 13]
    const float* __restrict__ cat_t1,      // [26, V]
    const float* __restrict__ cat_t2,      // [26, V, 64]
    const float* __restrict__ cont_t1,     // [13]
    const float* __restrict__ cont_t2)     // [13, 64]
{
    int b = blockIdx.x;
    int d = threadIdx.x;   // 0..63

    __shared__ int   s_idx[F_CAT];
    __shared__ float s_cont[F_CONT];
    if (d < F_CAT)                  s_idx[d]       = cat_feats[(size_t)b * F_CAT + d];
    if (d >= 32 && d < 32 + F_CONT) s_cont[d - 32] = cont_feats[(size_t)b * F_CONT + (d - 32)];
    __syncthreads();

    float s = 0.f, ss = 0.f;
    float* Erow = g_E + (size_t)b * IN_DIM;

    #pragma unroll
    for (int f = 0; f < F_CAT; f++) {
        float v = __ldg(cat_t2 + ((size_t)f * VOCAB + s_idx[f]) * DIM + d);
        Erow[f * DIM + d] = v;
        s += v; ss += v * v;
    }
    #pragma unroll
    for (int j = 0; j < F_CONT; j++) {
        float v = cont_t2[j * DIM + d] * s_cont[j];
        Erow[(F_CAT + j) * DIM + d] = v;
        s += v; ss += v * v;
    }

    // fm_second contribution for dim d
    float tot = 0.5f * (s * s - ss);
    // fm_first: threads 0..25 handle cat, threads 32..44 handle cont
    if (d < F_CAT)                   tot += cat_t1[(size_t)d * VOCAB + s_idx[d]];
    if (d >= 32 && d < 32 + F_CONT)  tot += cont_t1[d - 32] * s_cont[d - 32];

    // reduce across 64 threads (2 warps)
    #pragma unroll
    for (int o = 16; o > 0; o >>= 1) tot += __shfl_xor_sync(0xFFFFFFFFu, tot, o);
    __shared__ float sred[2];
    if ((d & 31) == 0) sred[d >> 5] = tot;
    __syncthreads();
    if (d == 0) g_fm[b] = sred[0] + sred[1];
}

// ---------------- kernel 2: SGEMM  C[M,N] = A[M,K] @ W[K,N] + bias[N] ----------------
// 128x128x16 block tile, double-buffered smem, 8x8 register tile, 256 threads.
// One __syncthreads() per 16-K slab; global loads for slab t+1 overlap compute of slab t.
__global__ __launch_bounds__(256) void sgemm_bias_kernel(
    const float* __restrict__ A, const float* __restrict__ W,
    const float* __restrict__ bias, float* __restrict__ C,
    int M, int N, int K)
{
    __shared__ float As[2][16][128];   // A stored transposed: As[k][row]
    __shared__ float Bs[2][16][128];   // Bs[k][col]

    const int tid = threadIdx.x;
    const int blockRow = blockIdx.y * 128;
    const int blockCol = blockIdx.x * 128;

    // A tile loads: 128 rows x 16 cols = 512 float4; ids {tid, tid+256}
    const int rowA0 = tid >> 2,          c4A = (tid & 3);          // id0 = tid
    const int rowA1 = (tid + 256) >> 2;                            // id1 (same c4A: (tid+256)&3 == tid&3)
    // B tile loads: 16 rows x 128 cols = 512 float4; ids {tid, tid+256}
    const int rowB0 = tid >> 5,          c4B = (tid & 31);
    const int rowB1 = (tid + 256) >> 5;

    const int tx = tid & 15, ty = tid >> 4;   // 16x16 thread grid, 8x8 microtile each

    const float* Aptr0 = A + (size_t)(blockRow + rowA0) * K + c4A * 4;
    const float* Aptr1 = A + (size_t)(blockRow + rowA1) * K + c4A * 4;
    const float* Bptr0 = W + (size_t)rowB0 * N + blockCol + c4B * 4;
    const float* Bptr1 = W + (size_t)rowB1 * N + blockCol + c4B * 4;

    float acc[8][8];
    #pragma unroll
    for (int i = 0; i < 8; i++)
        #pragma unroll
        for (int j = 0; j < 8; j++) acc[i][j] = 0.f;

    // ---- preload slab 0 into buffer 0 ----
    {
        float4 a0 = *(const float4*)(Aptr0);
        float4 a1 = *(const float4*)(Aptr1);
        float4 b0 = *(const float4*)(Bptr0);
        float4 b1 = *(const float4*)(Bptr1);
        As[0][c4A * 4 + 0][rowA0] = a0.x;  As[0][c4A * 4 + 1][rowA0] = a0.y;
        As[0][c4A * 4 + 2][rowA0] = a0.z;  As[0][c4A * 4 + 3][rowA0] = a0.w;
        As[0][c4A * 4 + 0][rowA1] = a1.x;  As[0][c4A * 4 + 1][rowA1] = a1.y;
        As[0][c4A * 4 + 2][rowA1] = a1.z;  As[0][c4A * 4 + 3][rowA1] = a1.w;
        *(float4*)&Bs[0][rowB0][c4B * 4] = b0;
        *(float4*)&Bs[0][rowB1][c4B * 4] = b1;
    }
    __syncthreads();

    const int T = K / 16;
    int buf = 0;
    for (int t = 0; t < T; t++) {
        float4 a0, a1, b0, b1;
        const bool more = (t + 1 < T);
        if (more) {
            int k0 = (t + 1) * 16;
            a0 = *(const float4*)(Aptr0 + k0);
            a1 = *(const float4*)(Aptr1 + k0);
            b0 = *(const float4*)(Bptr0 + (size_t)k0 * N);
            b1 = *(const float4*)(Bptr1 + (size_t)k0 * N);
        }

        #pragma unroll
        for (int kk = 0; kk < 16; kk++) {
            float af[8], bf[8];
            *(float4*)&af[0] = *(const float4*)&As[buf][kk][ty * 8 + 0];
            *(float4*)&af[4] = *(const float4*)&As[buf][kk][ty * 8 + 4];
            *(float4*)&bf[0] = *(const float4*)&Bs[buf][kk][tx * 8 + 0];
            *(float4*)&bf[4] = *(const float4*)&Bs[buf][kk][tx * 8 + 4];
            #pragma unroll
            for (int i = 0; i < 8; i++)
                #pragma unroll
                for (int j = 0; j < 8; j++)
                    acc[i][j] = fmaf(af[i], bf[j], acc[i][j]);
        }

        if (more) {
            int nb = buf ^ 1;
            As[nb][c4A * 4 + 0][rowA0] = a0.x;  As[nb][c4A * 4 + 1][rowA0] = a0.y;
            As[nb][c4A * 4 + 2][rowA0] = a0.z;  As[nb][c4A * 4 + 3][rowA0] = a0.w;
            As[nb][c4A * 4 + 0][rowA1] = a1.x;  As[nb][c4A * 4 + 1][rowA1] = a1.y;
            As[nb][c4A * 4 + 2][rowA1] = a1.z;  As[nb][c4A * 4 + 3][rowA1] = a1.w;
            *(float4*)&Bs[nb][rowB0][c4B * 4] = b0;
            *(float4*)&Bs[nb][rowB1][c4B * 4] = b1;
            __syncthreads();
            buf = nb;
        }
    }

    #pragma unroll
    for (int i = 0; i < 8; i++) {
        int row = blockRow + ty * 8 + i;
        float* Crow = C + (size_t)row * N + blockCol + tx * 8;
        #pragma unroll
        for (int j = 0; j < 8; j += 4) {
            float4 v;
            int c = blockCol + tx * 8 + j;
            v.x = acc[i][j + 0] + bias[c + 0];
            v.y = acc[i][j + 1] + bias[c + 1];
            v.z = acc[i][j + 2] + bias[c + 2];
            v.w = acc[i][j + 3] + bias[c + 3];
            *(float4*)(Crow + j) = v;
        }
    }
}

// ---------------- kernel 3: BN stats, stage 1 (deterministic, no atomics) ----------------
// grid (N/256, 64): block sums 256 rows for 256 columns -> partials[rowblk][col]
__global__ __launch_bounds__(256) void stats_part_kernel(
    const float* __restrict__ Z, float* __restrict__ psum, float* __restrict__ pss, int N)
{
    int h  = blockIdx.x * 256 + threadIdx.x;
    int r0 = blockIdx.y * 256;
    float s = 0.f, q = 0.f;
    #pragma unroll 8
    for (int r = r0; r < r0 + 256; r++) {
        float v = Z[(size_t)r * N + h];
        s += v; q += v * v;
    }
    psum[(size_t)blockIdx.y * N + h] = s;
    pss [(size_t)blockIdx.y * N + h] = q;
}

// ---------------- kernel 4: BN stats, stage 2 ----------------
__global__ __launch_bounds__(256) void stats_reduce_kernel(
    const float* __restrict__ psum, const float* __restrict__ pss,
    float* __restrict__ sum, float* __restrict__ ss, int N)
{
    int h = blockIdx.x * 256 + threadIdx.x;
    float s = 0.f, q = 0.f;
    #pragma unroll
    for (int i = 0; i < 64; i++) {
        s += psum[(size_t)i * N + h];
        q += pss [(size_t)i * N + h];
    }
    sum[h] = s; ss[h] = q;
}

// ---------------- kernel 5: in-place BN + ReLU ----------------
__global__ __launch_bounds__(256) void bn_relu_kernel(
    float* __restrict__ Z, const float* __restrict__ sum, const float* __restrict__ ss,
    const float* __restrict__ g, const float* __restrict__ be, int N)
{
    size_t idx = (size_t)blockIdx.x * 256 + threadIdx.x;
    int col = (int)(idx & (size_t)(N - 1));     // N is a power of 2
    float mu  = sum[col] * (1.f / B_SZ);
    float var = ss[col] * (1.f / B_SZ) - mu * mu;
    float sc  = g[col] * rsqrtf(var + BN_EPS);
    float v   = (Z[idx] - mu) * sc + be[col];
    Z[idx] = fmaxf(v, 0.f);
}

// ---------------- kernel 6: final dot + sigmoid, out[B,2] ----------------
__global__ __launch_bounds__(256) void final_kernel(
    const float* __restrict__ W3, const float* __restrict__ b3,
    const float* __restrict__ bias0, float* __restrict__ out)
{
    int gwarp = (blockIdx.x * blockDim.x + threadIdx.x) >> 5;
    int lane  = threadIdx.x & 31;
    if (gwarp >= B_SZ) return;
    const float* h = g_Z2 + (size_t)gwarp * H2N;
    float s = 0.f;
    #pragma unroll
    for (int i = lane; i < H2N; i += 32) s += h[i] * W3[i];
    #pragma unroll
    for (int o = 16; o > 0; o >>= 1) s += __shfl_xor_sync(0xFFFFFFFFu, s, o);
    if (lane == 0) {
        float x = bias0[0] + g_fm[gwarp] + s + b3[0];
        float p = 1.f / (1.f + expf(-x));
        out[(size_t)gwarp * 2 + 0] = 1.f - p;
        out[(size_t)gwarp * 2 + 1] = p;
    }
}

// ---------------- launch ----------------
extern "C" void kernel_launch(void* const* d_in, const int* in_sizes, int n_in,
                              void* d_out, int out_size)
{
    const int*   cat_feats  = (const int*)  d_in[0];
    const float* cont_feats = (const float*)d_in[1];
    const float* bias0      = (const float*)d_in[2];
    const float* cat_t1     = (const float*)d_in[3];
    const float* cat_t2     = (const float*)d_in[4];
    const float* cont_t1    = (const float*)d_in[5];
    const float* cont_t2    = (const float*)d_in[6];
    const float* W1         = (const float*)d_in[7];
    const float* b1         = (const float*)d_in[8];
    const float* g1         = (const float*)d_in[9];
    const float* be1        = (const float*)d_in[10];
    const float* W2         = (const float*)d_in[11];
    const float* b2         = (const float*)d_in[12];
    const float* g2         = (const float*)d_in[13];
    const float* be2        = (const float*)d_in[14];
    const float* W3         = (const float*)d_in[15];
    const float* b3         = (const float*)d_in[16];
    float* out = (float*)d_out;

    float *pE, *pZ1, *pZ2, *ppsum, *ppss, *psum, *pss;
    cudaGetSymbolAddress((void**)&pE,    g_E);
    cudaGetSymbolAddress((void**)&pZ1,   g_Z1);
    cudaGetSymbolAddress((void**)&pZ2,   g_Z2);
    cudaGetSymbolAddress((void**)&ppsum, g_psum);
    cudaGetSymbolAddress((void**)&ppss,  g_pss);
    cudaGetSymbolAddress((void**)&psum,  g_sum);
    cudaGetSymbolAddress((void**)&pss,   g_ss);

    // 1. embeddings + FM
    embed_fm_kernel<<<B_SZ, 64>>>(cat_feats, cont_feats, cat_t1, cat_t2, cont_t1, cont_t2);

    // 2. layer 1: Z1 = E @ W1 + b1
    sgemm_bias_kernel<<<dim3(H1N / 128, B_SZ / 128), 256>>>(pE, W1, b1, pZ1, B_SZ, H1N, IN_DIM);
    stats_part_kernel  <<<dim3(H1N / 256, 64), 256>>>(pZ1, ppsum, ppss, H1N);
    stats_reduce_kernel<<<H1N / 256, 256>>>(ppsum, ppss, psum, pss, H1N);
    bn_relu_kernel<<<(int)(((size_t)B_SZ * H1N) / 256), 256>>>(pZ1, psum, pss, g1, be1, H1N);

    // 3. layer 2: Z2 = H1 @ W2 + b2
    sgemm_bias_kernel<<<dim3(H2N / 128, B_SZ / 128), 256>>>(pZ1, W2, b2, pZ2, B_SZ, H2N, H1N);
    stats_part_kernel  <<<dim3(H2N / 256, 64), 256>>>(pZ2, ppsum, ppss, H2N);
    stats_reduce_kernel<<<H2N / 256, 256>>>(ppsum, ppss, psum, pss, H2N);
    bn_relu_kernel<<<(int)(((size_t)B_SZ * H2N) / 256), 256>>>(pZ2, psum, pss, g2, be2, H2N);

    // 4. head
    final_kernel<<<B_SZ / 8, 256>>>(W3, b3, bias0, out);
}

// round 6
// speedup vs baseline: 1.8747x; 1.8747x over previous
#include <cuda_runtime.h>
#include <cuda_bf16.h>
#include <math.h>
#include <stdint.h>

#define B_SZ   16384
#define F_CAT  26
#define F_CONT 13
#define VOCAB  100000
#define DIM    64
#define IN_DIM 2496      // (26+13)*64
#define H1N    1024
#define H2N    512
#define BN_EPS 1e-5f

// ---------------- device scratch ----------------
__device__ __align__(128) __nv_bfloat16 g_Ehi [(size_t)B_SZ * IN_DIM];
__device__ __align__(128) __nv_bfloat16 g_Elo [(size_t)B_SZ * IN_DIM];
__device__ __align__(128) __nv_bfloat16 g_W1t_hi[(size_t)H1N * IN_DIM];   // [N,K]
__device__ __align__(128) __nv_bfloat16 g_W1t_lo[(size_t)H1N * IN_DIM];
__device__ __align__(128) __nv_bfloat16 g_W2t_hi[(size_t)H2N * H1N];
__device__ __align__(128) __nv_bfloat16 g_W2t_lo[(size_t)H2N * H1N];
__device__ __align__(128) float         g_Z1 [(size_t)B_SZ * H1N];
__device__ __align__(128) __nv_bfloat16 g_Z1hi[(size_t)B_SZ * H1N];
__device__ __align__(128) __nv_bfloat16 g_Z1lo[(size_t)B_SZ * H1N];
__device__ __align__(128) float         g_Z2 [(size_t)B_SZ * H2N];
__device__ __align__(128) float g_fm[B_SZ];
__device__ __align__(128) float g_psum[64 * H1N];
__device__ __align__(128) float g_pss [64 * H1N];
__device__ __align__(128) float g_sum [H1N];
__device__ __align__(128) float g_ss  [H1N];

// ---------------- helpers ----------------
__device__ __forceinline__ uint32_t smem_u32(const void* p) {
    uint32_t a;
    asm("{ .reg .u64 t; cvta.to.shared.u64 t, %1; cvt.u32.u64 %0, t; }" : "=r"(a) : "l"(p));
    return a;
}
__device__ __forceinline__ void ldsm4(uint32_t* r, uint32_t addr) {
    asm volatile("ldmatrix.sync.aligned.m8n8.x4.shared.b16 {%0,%1,%2,%3}, [%4];"
        : "=r"(r[0]), "=r"(r[1]), "=r"(r[2]), "=r"(r[3]) : "r"(addr));
}
__device__ __forceinline__ void mma16816(float* c, const uint32_t* a, uint32_t b0, uint32_t b1) {
    asm volatile("mma.sync.aligned.m16n8k16.row.col.f32.bf16.bf16.f32 "
        "{%0,%1,%2,%3}, {%4,%5,%6,%7}, {%8,%9}, {%0,%1,%2,%3};"
        : "+f"(c[0]), "+f"(c[1]), "+f"(c[2]), "+f"(c[3])
        : "r"(a[0]), "r"(a[1]), "r"(a[2]), "r"(a[3]), "r"(b0), "r"(b1));
}

// smem tile: 64B rows (32 bf16), XOR swizzle keeps STS.128 and ldmatrix conflict-free
#define SW(r, cb) ((uint32_t)((r) * 64 + (((cb) ^ ((((r) >> 1) & 3) << 4)))))

// smem layout per buffer: Ahi 8K | Alo 8K | Bhi 8K | Blo 8K = 32KB; x2 buffers
#define T_AHI  0
#define T_ALO  (8 * 1024)
#define T_BHI  (16 * 1024)
#define T_BLO  (24 * 1024)
#define BUFSZ  (32 * 1024)
#define GEMM_SMEM (2 * BUFSZ)

// ---------------- tensor-core GEMM: C[M,Nfull] = (Ahi+Alo)@(Bhi+Blo)^T + bias ----------------
// A: [M,K] bf16 hi/lo row-major. B: [Nfull,K] bf16 hi/lo row-major (transposed weights).
// CTA 128x128, warp 32x64 (warpM=wid&3, warpN=wid>>2), K-chunk 32, double buffered.
__global__ __launch_bounds__(256) void hmma_gemm_kernel(
    const __nv_bfloat16* __restrict__ Ahi, const __nv_bfloat16* __restrict__ Alo,
    const __nv_bfloat16* __restrict__ Bhi, const __nv_bfloat16* __restrict__ Blo,
    const float* __restrict__ bias, float* __restrict__ C,
    int Nfull, int K)
{
    extern __shared__ char sm[];
    const uint32_t sbase = smem_u32(sm);
    const int tid   = threadIdx.x;
    const int lane  = tid & 31;
    const int wid   = tid >> 5;
    const int warpM = wid & 3;        // 4 warps along M, 32 rows each
    const int warpN = wid >> 2;       // 2 warps along N, 64 cols each
    const int row0  = blockIdx.y * 128;
    const int n0    = blockIdx.x * 128;

    float acc[2][8][4];
    #pragma unroll
    for (int i = 0; i < 2; i++)
        #pragma unroll
        for (int j = 0; j < 8; j++)
            #pragma unroll
            for (int q = 0; q < 4; q++) acc[i][j][q] = 0.f;

    // per-thread load slots: chunks tid and tid+256 of 512 (r = id>>2, 16B col (id&3)*16)
    const int r_0 = tid >> 2,           cb_0 = (tid & 3) << 4;
    const int r_1 = (tid + 256) >> 2,   cb_1 = cb_0;          // (tid+256)&3 == tid&3

    uint4 ahr[2], alr[2], bhr[2], blr[2];

    const int T = K >> 5;   // K / 32

    // ---- load chunk t into regs ----
    auto LOAD = [&](int t) {
        const int k0 = t << 5;
        {
            size_t ga = (size_t)(row0 + r_0) * K + k0 + (cb_0 >> 1);
            ahr[0] = *(const uint4*)(Ahi + ga);  alr[0] = *(const uint4*)(Alo + ga);
            size_t gb = (size_t)(n0 + r_0) * K + k0 + (cb_0 >> 1);
            bhr[0] = *(const uint4*)(Bhi + gb);  blr[0] = *(const uint4*)(Blo + gb);
        }
        {
            size_t ga = (size_t)(row0 + r_1) * K + k0 + (cb_1 >> 1);
            ahr[1] = *(const uint4*)(Ahi + ga);  alr[1] = *(const uint4*)(Alo + ga);
            size_t gb = (size_t)(n0 + r_1) * K + k0 + (cb_1 >> 1);
            bhr[1] = *(const uint4*)(Bhi + gb);  blr[1] = *(const uint4*)(Blo + gb);
        }
    };
    // ---- store staged regs into buffer ----
    auto STORE = [&](int buf) {
        char* b = sm + buf * BUFSZ;
        uint32_t o0 = SW(r_0, cb_0), o1 = SW(r_1, cb_1);
        *(uint4*)(b + T_AHI + o0) = ahr[0];  *(uint4*)(b + T_ALO + o0) = alr[0];
        *(uint4*)(b + T_BHI + o0) = bhr[0];  *(uint4*)(b + T_BLO + o0) = blr[0];
        *(uint4*)(b + T_AHI + o1) = ahr[1];  *(uint4*)(b + T_ALO + o1) = alr[1];
        *(uint4*)(b + T_BHI + o1) = bhr[1];  *(uint4*)(b + T_BLO + o1) = blr[1];
    };
    // ---- compute one 32-K chunk from buffer ----
    auto COMPUTE = [&](int buf) {
        const uint32_t b = sbase + buf * BUFSZ;
        const int lrow = lane & 15;
        const int lext = (lane >> 4) << 4;   // +16B for upper 8 cols
        #pragma unroll
        for (int ks = 0; ks < 2; ks++) {
            const int kb = ks * 32 + lext;
            uint32_t aH[2][4], aL[2][4], bH[16], bL[16];
            #pragma unroll
            for (int im = 0; im < 2; im++) {
                int r = warpM * 32 + im * 16 + lrow;
                ldsm4(aH[im], b + T_AHI + SW(r, kb));
                ldsm4(aL[im], b + T_ALO + SW(r, kb));
            }
            #pragma unroll
            for (int g = 0; g < 4; g++) {
                int r = warpN * 64 + g * 16 + lrow;
                ldsm4(&bH[g * 4], b + T_BHI + SW(r, kb));
                ldsm4(&bL[g * 4], b + T_BLO + SW(r, kb));
            }
            #pragma unroll
            for (int im = 0; im < 2; im++)
                #pragma unroll
                for (int jn = 0; jn < 8; jn++) {
                    int g = jn >> 1, o = jn & 1;
                    uint32_t h0 = bH[4 * g + o], h1 = bH[4 * g + 2 + o];
                    uint32_t l0 = bL[4 * g + o], l1 = bL[4 * g + 2 + o];
                    mma16816(acc[im][jn], aH[im], h0, h1);
                    mma16816(acc[im][jn], aH[im], l0, l1);
                    mma16816(acc[im][jn], aL[im], h0, h1);
                }
        }
    };

    LOAD(0); STORE(0); __syncthreads();
    for (int t = 0; t < T; t++) {
        if (t + 1 < T) LOAD(t + 1);
        COMPUTE(t & 1);
        if (t + 1 < T) { STORE((t & 1) ^ 1); __syncthreads(); }
    }

    // epilogue: acc -> C (+bias)
    #pragma unroll
    for (int im = 0; im < 2; im++) {
        int rA = row0 + warpM * 32 + im * 16 + (lane >> 2);
        #pragma unroll
        for (int jn = 0; jn < 8; jn++) {
            int col = n0 + warpN * 64 + jn * 8 + (lane & 3) * 2;
            float b0 = __ldg(bias + col), b1 = __ldg(bias + col + 1);
            float2 v0 = make_float2(acc[im][jn][0] + b0, acc[im][jn][1] + b1);
            float2 v1 = make_float2(acc[im][jn][2] + b0, acc[im][jn][3] + b1);
            *(float2*)(C + (size_t)rA * Nfull + col)       = v0;
            *(float2*)(C + (size_t)(rA + 8) * Nfull + col) = v1;
        }
    }
}

// ---------------- kernel: split fp32 -> bf16 hi/lo with transpose (for W) ----------------
__global__ __launch_bounds__(256) void convert_transpose_w(
    const float* __restrict__ W,          // [K, N]
    __nv_bfloat16* __restrict__ Wt_hi,    // [N, K]
    __nv_bfloat16* __restrict__ Wt_lo,
    int K, int N)
{
    __shared__ float tile[32][33];
    int n0 = blockIdx.x * 32, k0 = blockIdx.y * 32;
    int tx = threadIdx.x & 31, ty = threadIdx.x >> 5;  // 32 x 8
    #pragma unroll
    for (int i = ty; i < 32; i += 8)
        tile[i][tx] = W[(size_t)(k0 + i) * N + n0 + tx];
    __syncthreads();
    #pragma unroll
    for (int i = ty; i < 32; i += 8) {
        float v = tile[tx][i];                      // = W[k0+tx][n0+i]
        __nv_bfloat16 hi = __float2bfloat16(v);
        __nv_bfloat16 lo = __float2bfloat16(v - __bfloat162float(hi));
        size_t o = (size_t)(n0 + i) * K + k0 + tx;
        Wt_hi[o] = hi;
        Wt_lo[o] = lo;
    }
}

// ---------------- kernel: embedding gather + FM + E (bf16 hi/lo) ----------------
__global__ __launch_bounds__(64) void embed_fm_kernel(
    const int*   __restrict__ cat_feats, const float* __restrict__ cont_feats,
    const float* __restrict__ cat_t1,    const float* __restrict__ cat_t2,
    const float* __restrict__ cont_t1,   const float* __restrict__ cont_t2)
{
    int b = blockIdx.x;
    int d = threadIdx.x;

    __shared__ int   s_idx[F_CAT];
    __shared__ float s_cont[F_CONT];
    if (d < F_CAT)                  s_idx[d]       = cat_feats[(size_t)b * F_CAT + d];
    if (d >= 32 && d < 32 + F_CONT) s_cont[d - 32] = cont_feats[(size_t)b * F_CONT + (d - 32)];
    __syncthreads();

    float s = 0.f, ss = 0.f;
    __nv_bfloat16* Ehi = g_Ehi + (size_t)b * IN_DIM;
    __nv_bfloat16* Elo = g_Elo + (size_t)b * IN_DIM;

    #pragma unroll
    for (int f = 0; f < F_CAT; f++) {
        float v = __ldg(cat_t2 + ((size_t)f * VOCAB + s_idx[f]) * DIM + d);
        __nv_bfloat16 hi = __float2bfloat16(v);
        Ehi[f * DIM + d] = hi;
        Elo[f * DIM + d] = __float2bfloat16(v - __bfloat162float(hi));
        s += v; ss += v * v;
    }
    #pragma unroll
    for (int j = 0; j < F_CONT; j++) {
        float v = cont_t2[j * DIM + d] * s_cont[j];
        __nv_bfloat16 hi = __float2bfloat16(v);
        Ehi[(F_CAT + j) * DIM + d] = hi;
        Elo[(F_CAT + j) * DIM + d] = __float2bfloat16(v - __bfloat162float(hi));
        s += v; ss += v * v;
    }

    float tot = 0.5f * (s * s - ss);
    if (d < F_CAT)                  tot += cat_t1[(size_t)d * VOCAB + s_idx[d]];
    if (d >= 32 && d < 32 + F_CONT) tot += cont_t1[d - 32] * s_cont[d - 32];

    #pragma unroll
    for (int o = 16; o > 0; o >>= 1) tot += __shfl_xor_sync(0xFFFFFFFFu, tot, o);
    __shared__ float sred[2];
    if ((d & 31) == 0) sred[d >> 5] = tot;
    __syncthreads();
    if (d == 0) g_fm[b] = sred[0] + sred[1];
}

// ---------------- BN stats (two-stage deterministic) ----------------
__global__ __launch_bounds__(256) void stats_part_kernel(
    const float* __restrict__ Z, float* __restrict__ psum, float* __restrict__ pss, int N)
{
    int h  = blockIdx.x * 256 + threadIdx.x;
    int r0 = blockIdx.y * 256;
    float s = 0.f, q = 0.f;
    #pragma unroll 8
    for (int r = r0; r < r0 + 256; r++) {
        float v = Z[(size_t)r * N + h];
        s += v; q += v * v;
    }
    psum[(size_t)blockIdx.y * N + h] = s;
    pss [(size_t)blockIdx.y * N + h] = q;
}

__global__ __launch_bounds__(256) void stats_reduce_kernel(
    const float* __restrict__ psum, const float* __restrict__ pss,
    float* __restrict__ sum, float* __restrict__ ss, int N)
{
    int h = blockIdx.x * 256 + threadIdx.x;
    float s = 0.f, q = 0.f;
    #pragma unroll
    for (int i = 0; i < 64; i++) {
        s += psum[(size_t)i * N + h];
        q += pss [(size_t)i * N + h];
    }
    sum[h] = s; ss[h] = q;
}

// ---------------- BN + ReLU -> bf16 hi/lo (layer 1) ----------------
__global__ __launch_bounds__(256) void bn_relu_split_kernel(
    const float* __restrict__ Z, __nv_bfloat16* __restrict__ Zhi, __nv_bfloat16* __restrict__ Zlo,
    const float* __restrict__ sum, const float* __restrict__ ss,
    const float* __restrict__ g, const float* __restrict__ be, int N)
{
    size_t idx = (size_t)blockIdx.x * 256 + threadIdx.x;
    int col = (int)(idx & (size_t)(N - 1));
    float mu  = sum[col] * (1.f / B_SZ);
    float var = ss[col] * (1.f / B_SZ) - mu * mu;
    float sc  = g[col] * rsqrtf(var + BN_EPS);
    float v   = fmaxf((Z[idx] - mu) * sc + be[col], 0.f);
    __nv_bfloat16 hi = __float2bfloat16(v);
    Zhi[idx] = hi;
    Zlo[idx] = __float2bfloat16(v - __bfloat162float(hi));
}

// ---------------- BN + ReLU in place fp32 (layer 2) ----------------
__global__ __launch_bounds__(256) void bn_relu_kernel(
    float* __restrict__ Z, const float* __restrict__ sum, const float* __restrict__ ss,
    const float* __restrict__ g, const float* __restrict__ be, int N)
{
    size_t idx = (size_t)blockIdx.x * 256 + threadIdx.x;
    int col = (int)(idx & (size_t)(N - 1));
    float mu  = sum[col] * (1.f / B_SZ);
    float var = ss[col] * (1.f / B_SZ) - mu * mu;
    float sc  = g[col] * rsqrtf(var + BN_EPS);
    float v   = (Z[idx] - mu) * sc + be[col];
    Z[idx] = fmaxf(v, 0.f);
}

// ---------------- head ----------------
__global__ __launch_bounds__(256) void final_kernel(
    const float* __restrict__ W3, const float* __restrict__ b3,
    const float* __restrict__ bias0, float* __restrict__ out)
{
    int gwarp = (blockIdx.x * blockDim.x + threadIdx.x) >> 5;
    int lane  = threadIdx.x & 31;
    if (gwarp >= B_SZ) return;
    const float* h = g_Z2 + (size_t)gwarp * H2N;
    float s = 0.f;
    #pragma unroll
    for (int i = lane; i < H2N; i += 32) s += h[i] * W3[i];
    #pragma unroll
    for (int o = 16; o > 0; o >>= 1) s += __shfl_xor_sync(0xFFFFFFFFu, s, o);
    if (lane == 0) {
        float x = bias0[0] + g_fm[gwarp] + s + b3[0];
        float p = 1.f / (1.f + expf(-x));
        out[(size_t)gwarp * 2 + 0] = 1.f - p;
        out[(size_t)gwarp * 2 + 1] = p;
    }
}

// ---------------- launch ----------------
extern "C" void kernel_launch(void* const* d_in, const int* in_sizes, int n_in,
                              void* d_out, int out_size)
{
    const int*   cat_feats  = (const int*)  d_in[0];
    const float* cont_feats = (const float*)d_in[1];
    const float* bias0      = (const float*)d_in[2];
    const float* cat_t1     = (const float*)d_in[3];
    const float* cat_t2     = (const float*)d_in[4];
    const float* cont_t1    = (const float*)d_in[5];
    const float* cont_t2    = (const float*)d_in[6];
    const float* W1         = (const float*)d_in[7];
    const float* b1         = (const float*)d_in[8];
    const float* g1         = (const float*)d_in[9];
    const float* be1        = (const float*)d_in[10];
    const float* W2         = (const float*)d_in[11];
    const float* b2         = (const float*)d_in[12];
    const float* g2         = (const float*)d_in[13];
    const float* be2        = (const float*)d_in[14];
    const float* W3         = (const float*)d_in[15];
    const float* b3         = (const float*)d_in[16];
    float* out = (float*)d_out;

    __nv_bfloat16 *pEhi, *pElo, *pW1h, *pW1l, *pW2h, *pW2l, *pZ1h, *pZ1l;
    float *pZ1, *pZ2, *ppsum, *ppss, *psum, *pss;
    cudaGetSymbolAddress((void**)&pEhi,  g_Ehi);
    cudaGetSymbolAddress((void**)&pElo,  g_Elo);
    cudaGetSymbolAddress((void**)&pW1h,  g_W1t_hi);
    cudaGetSymbolAddress((void**)&pW1l,  g_W1t_lo);
    cudaGetSymbolAddress((void**)&pW2h,  g_W2t_hi);
    cudaGetSymbolAddress((void**)&pW2l,  g_W2t_lo);
    cudaGetSymbolAddress((void**)&pZ1,   g_Z1);
    cudaGetSymbolAddress((void**)&pZ1h,  g_Z1hi);
    cudaGetSymbolAddress((void**)&pZ1l,  g_Z1lo);
    cudaGetSymbolAddress((void**)&pZ2,   g_Z2);
    cudaGetSymbolAddress((void**)&ppsum, g_psum);
    cudaGetSymbolAddress((void**)&ppss,  g_pss);
    cudaGetSymbolAddress((void**)&psum,  g_sum);
    cudaGetSymbolAddress((void**)&pss,   g_ss);

    cudaFuncSetAttribute(hmma_gemm_kernel, cudaFuncAttributeMaxDynamicSharedMemorySize, GEMM_SMEM);

    // weight convert + transpose (hi/lo bf16)
    convert_transpose_w<<<dim3(H1N / 32, IN_DIM / 32), 256>>>(W1, pW1h, pW1l, IN_DIM, H1N);
    convert_transpose_w<<<dim3(H2N / 32, H1N / 32),    256>>>(W2, pW2h, pW2l, H1N, H2N);

    // embeddings + FM
    embed_fm_kernel<<<B_SZ, 64>>>(cat_feats, cont_feats, cat_t1, cat_t2, cont_t1, cont_t2);

    // layer 1: Z1 = E @ W1 + b1  (HMMA split-bf16)
    hmma_gemm_kernel<<<dim3(H1N / 128, B_SZ / 128), 256, GEMM_SMEM>>>(
        pEhi, pElo, pW1h, pW1l, b1, pZ1, H1N, IN_DIM);
    stats_part_kernel  <<<dim3(H1N / 256, 64), 256>>>(pZ1, ppsum, ppss, H1N);
    stats_reduce_kernel<<<H1N / 256, 256>>>(ppsum, ppss, psum, pss, H1N);
    bn_relu_split_kernel<<<(int)(((size_t)B_SZ * H1N) / 256), 256>>>(
        pZ1, pZ1h, pZ1l, psum, pss, g1, be1, H1N);

    // layer 2: Z2 = H1 @ W2 + b2
    hmma_gemm_kernel<<<dim3(H2N / 128, B_SZ / 128), 256, GEMM_SMEM>>>(
        pZ1h, pZ1l, pW2h, pW2l, b2, pZ2, H2N, H1N);
    stats_part_kernel  <<<dim3(H2N / 256, 64), 256>>>(pZ2, ppsum, ppss, H2N);
    stats_reduce_kernel<<<H2N / 256, 256>>>(ppsum, ppss, psum, pss, H2N);
    bn_relu_kernel<<<(int)(((size_t)B_SZ * H2N) / 256), 256>>>(pZ2, psum, pss, g2, be2, H2N);

    // head
    final_kernel<<<B_SZ / 8, 256>>>(W3, b3, bias0, out);
}